// round 16
// baseline (speedup 1.0000x reference)
#include <cuda_runtime.h>
#include <cuda_fp16.h>
#include <math.h>
#include <stdint.h>

#define EMB   2048
#define NH    16
#define HD    128
#define BATCH 4
#define SEQ   2048
#define MTOT  (BATCH*SEQ)   // 8192 rows
#define GK    2048          // GEMM K (fixed)

// Scratch (device globals -- allocation-free per harness rules)
__device__ float g_q[(size_t)MTOT * EMB];
__device__ float g_k[(size_t)MTOT * EMB];
__device__ float g_v[(size_t)MTOT * EMB];
__device__ float g_ctx[(size_t)MTOT * EMB];
// fp16 staging
__device__ __half g_xh[(size_t)MTOT * EMB];
__device__ __half g_xl[(size_t)MTOT * EMB];
__device__ __half g_ch[(size_t)MTOT * EMB];
__device__ __half g_cl[(size_t)MTOT * EMB];
__device__ __half g_wqh[(size_t)EMB * EMB];
__device__ __half g_wkh[(size_t)EMB * EMB];
__device__ __half g_wvh[(size_t)EMB * EMB];
__device__ __half g_woh[(size_t)EMB * EMB];

// ===========================================================================
// PTX helpers (baseline sm_80+)
// ===========================================================================
__device__ __forceinline__ uint32_t smem_u32(const void* p) {
    uint32_t a;
    asm("{ .reg .u64 t; cvta.to.shared.u64 t, %1; cvt.u32.u64 %0, t; }" : "=r"(a) : "l"(p));
    return a;
}
__device__ __forceinline__ void ldsm4(uint32_t* r, uint32_t addr) {
    asm volatile("ldmatrix.sync.aligned.m8n8.x4.shared.b16 {%0,%1,%2,%3}, [%4];"
        : "=r"(r[0]), "=r"(r[1]), "=r"(r[2]), "=r"(r[3]) : "r"(addr));
}
__device__ __forceinline__ void mma_f16(float* d, const uint32_t* a, uint32_t b0, uint32_t b1) {
    asm volatile("mma.sync.aligned.m16n8k16.row.col.f32.f16.f16.f32 "
        "{%0,%1,%2,%3}, {%4,%5,%6,%7}, {%8,%9}, {%0,%1,%2,%3};"
        : "+f"(d[0]), "+f"(d[1]), "+f"(d[2]), "+f"(d[3])
        : "r"(a[0]), "r"(a[1]), "r"(a[2]), "r"(a[3]), "r"(b0), "r"(b1));
}
__device__ __forceinline__ void cp16(uint32_t dst, const void* src) {
    asm volatile("cp.async.cg.shared.global [%0], [%1], 16;" :: "r"(dst), "l"(src));
}
#define CP_COMMIT() asm volatile("cp.async.commit_group;" ::: "memory")
#define CP_WAIT(n)  asm volatile("cp.async.wait_group %0;" :: "n"(n) : "memory")

// ===========================================================================
// Conversion kernels (hoisted out of the GEMM hot loop)
// ===========================================================================
__global__ void cvt_hilo(const float* __restrict__ in, __half* __restrict__ hi,
                         __half* __restrict__ lo, int n4)
{
    int i = blockIdx.x * blockDim.x + threadIdx.x;
    if (i >= n4) return;
    float4 v = *(const float4*)(in + (size_t)i * 4);
    __half2 h0 = __floats2half2_rn(v.x, v.y);
    __half2 h1 = __floats2half2_rn(v.z, v.w);
    __half2 e0 = __floats2half2_rn(v.x - __low2float(h0), v.y - __high2float(h0));
    __half2 e1 = __floats2half2_rn(v.z - __low2float(h1), v.w - __high2float(h1));
    *(__half2*)(hi + (size_t)i * 4)     = h0;
    *(__half2*)(hi + (size_t)i * 4 + 2) = h1;
    *(__half2*)(lo + (size_t)i * 4)     = e0;
    *(__half2*)(lo + (size_t)i * 4 + 2) = e1;
}
__global__ void cvt_hi(const float* __restrict__ in, __half* __restrict__ hi, int n4)
{
    int i = blockIdx.x * blockDim.x + threadIdx.x;
    if (i >= n4) return;
    float4 v = *(const float4*)(in + (size_t)i * 4);
    *(__half2*)(hi + (size_t)i * 4)     = __floats2half2_rn(v.x, v.y);
    *(__half2*)(hi + (size_t)i * 4 + 2) = __floats2half2_rn(v.z, v.w);
}

// ===========================================================================
// fp16 2-pass HMMA GEMM (NT), 3-stage cp.async pipeline.
// C[m][n] = sum_k (Ah+Al)[m][k] * Bh[n][k], fp32 accum.
// CTA tile 128x128, BK=32, 256 threads = 8 warps (2m x 4n), warp tile 64x32.
// AST = 40 fp16 (80B/row): 16B-aligned rows, conflict-free ldmatrix phases.
// gridDim.z selects among up to 3 (B, C) pairs -> one launch for Q/K/V.
// ===========================================================================
#define BM 128
#define BN 128
#define BKK 32
#define AST 40
#define NIT (GK / BKK)                 // 64
#define NSTG 3
#define TILEB (BM * AST * 2)           // 10240 bytes per tile array
#define BUFB  (3 * TILEB)              // 30720 bytes per stage
#define SMEM_GEMM (NSTG * BUFB)        // 92160

__global__ __launch_bounds__(256) void mma_gemm(const __half* __restrict__ Ah,
                                                const __half* __restrict__ Al,
                                                const __half* __restrict__ B0,
                                                const __half* __restrict__ B1,
                                                const __half* __restrict__ B2,
                                                float* __restrict__ C0,
                                                float* __restrict__ C1,
                                                float* __restrict__ C2,
                                                int M, int N)
{
    extern __shared__ char smem[];
    const uint32_t sb = smem_u32(smem);

    const __half* Bh = (blockIdx.z == 0) ? B0 : (blockIdx.z == 1) ? B1 : B2;
    float* C         = (blockIdx.z == 0) ? C0 : (blockIdx.z == 1) ? C1 : C2;

    const int tid  = threadIdx.x;
    const int lane = tid & 31;
    const int wid  = tid >> 5;
    const int m0 = blockIdx.y * BM;
    const int n0 = blockIdx.x * BN;
    const int wm = (wid & 1) * 64;
    const int wn = (wid >> 1) * 32;

    float acc[4][4][4];
#pragma unroll
    for (int i = 0; i < 4; i++)
#pragma unroll
        for (int j = 0; j < 4; j++)
#pragma unroll
            for (int r = 0; r < 4; r++) acc[i][j][r] = 0.f;

    // cp.async loader: per array 128 rows x 32 halfs; 256 thr -> 2 rows each.
    const int r0 = tid >> 2;           // rows 0..63 (+64 for second half)
    const int c0 = tid & 3;            // 16B chunk within the 64B row slab
    const __half* Ap = Ah + (size_t)(m0 + r0) * GK + c0 * 8;
    const __half* Lp = Al + (size_t)(m0 + r0) * GK + c0 * 8;
    const __half* Bp = Bh + (size_t)(n0 + r0) * GK + c0 * 8;
    const uint32_t sA = sb + r0 * 80 + c0 * 16;

#define ISSUE(it) do {                                                        \
        if ((it) < NIT) {                                                     \
            int kofs = (it) * BKK;                                            \
            uint32_t bb = ((it) % NSTG) * BUFB;                               \
            cp16(sA + bb,                      Ap + kofs);                    \
            cp16(sA + bb + (64*80),            Ap + kofs + (size_t)64 * GK);  \
            cp16(sA + bb + TILEB,              Lp + kofs);                    \
            cp16(sA + bb + TILEB + (64*80),    Lp + kofs + (size_t)64 * GK);  \
            cp16(sA + bb + 2*TILEB,            Bp + kofs);                    \
            cp16(sA + bb + 2*TILEB + (64*80),  Bp + kofs + (size_t)64 * GK);  \
        }                                                                     \
        CP_COMMIT();                                                          \
    } while (0)

    // ldmatrix base offsets (within a stage buffer)
    const uint32_t lrow = (lane & 15);
    const uint32_t lcol = (lane >> 4) * 8;
    const uint32_t aoff = ((wm + lrow) * AST + lcol) * 2;
    const uint32_t boff = ((wn + lrow) * AST + lcol) * 2 + 2 * TILEB;

    // Prologue: fill stages 0..NSTG-2
    ISSUE(0);
    ISSUE(1);

    for (int it = 0; it < NIT; it++) {
        // Issue stage it+NSTG-1 into buffer (it-1)%NSTG (freed by the sync
        // at the end of the previous iteration).
        ISSUE(it + NSTG - 1);
        CP_WAIT(NSTG - 1);             // group 'it' complete
        __syncthreads();

        const uint32_t bbase   = sb + (it % NSTG) * BUFB;
        const uint32_t a_base  = bbase + aoff;
        const uint32_t al_base = a_base + TILEB;
        const uint32_t b_base  = bbase + boff;

#pragma unroll
        for (int ks = 0; ks < 2; ks++) {
            const uint32_t kb = ks * 32;

            uint32_t afh[4][4], bfh[2][4];
#pragma unroll
            for (int mt = 0; mt < 4; mt++)
                ldsm4(afh[mt], a_base + mt * (16 * AST * 2) + kb);
#pragma unroll
            for (int nh = 0; nh < 2; nh++)
                ldsm4(bfh[nh], b_base + nh * (16 * AST * 2) + kb);

#pragma unroll
            for (int mt = 0; mt < 4; mt++)
#pragma unroll
                for (int nt = 0; nt < 4; nt++)
                    mma_f16(acc[mt][nt], afh[mt], bfh[nt >> 1][nt & 1], bfh[nt >> 1][(nt & 1) + 2]);

            uint32_t afl[4][4];
#pragma unroll
            for (int mt = 0; mt < 4; mt++)
                ldsm4(afl[mt], al_base + mt * (16 * AST * 2) + kb);
#pragma unroll
            for (int mt = 0; mt < 4; mt++)
#pragma unroll
                for (int nt = 0; nt < 4; nt++)
                    mma_f16(acc[mt][nt], afl[mt], bfh[nt >> 1][nt & 1], bfh[nt >> 1][(nt & 1) + 2]);
        }
        __syncthreads();               // buffer free for ISSUE next iter
    }

    const int erow = lane >> 2;
    const int ecol = (lane & 3) * 2;
#pragma unroll
    for (int mt = 0; mt < 4; mt++) {
#pragma unroll
        for (int nt = 0; nt < 4; nt++) {
            int row = m0 + wm + mt * 16 + erow;
            int col = n0 + wn + nt * 8 + ecol;
            *(float2*)(C + (size_t)row * N + col) =
                make_float2(acc[mt][nt][0], acc[mt][nt][1]);
            *(float2*)(C + (size_t)(row + 8) * N + col) =
                make_float2(acc[mt][nt][2], acc[mt][nt][3]);
        }
    }
#undef ISSUE
}

// ---------------------------------------------------------------------------
// RoPE (interleaved pairs), in-place on q and k.
// ---------------------------------------------------------------------------
__global__ void rope_kernel(float* __restrict__ q, float* __restrict__ k)
{
    int idx = blockIdx.x * blockDim.x + threadIdx.x;
    if (idx >= MTOT * NH * (HD / 2)) return;
    int i = idx & 63;
    int h = (idx >> 6) & 15;
    int m = idx >> 10;
    int s = m & (SEQ - 1);

    double freq = pow(10000.0, -(double)i / 64.0);
    float ang = (float)((double)s * freq);
    float sn, cs;
    sincosf(ang, &sn, &cs);

    size_t base = (size_t)m * EMB + h * HD + 2 * i;
    float q1 = q[base], q2 = q[base + 1];
    q[base]     = q1 * cs - q2 * sn;
    q[base + 1] = q2 * cs + q1 * sn;
    float k1 = k[base], k2 = k[base + 1];
    k[base]     = k1 * cs - k2 * sn;
    k[base + 1] = k2 * cs + k1 * sn;
}

// ---------------------------------------------------------------------------
// Flash attention (fp32), causal. One block per (q-tile of 64 rows, b*h).
// ---------------------------------------------------------------------------
#define BQ   64
#define BKV  64
#define QP   129
#define VP   132
#define SP   65

__global__ __launch_bounds__(256) void flash_kernel(const float* __restrict__ q,
                                                    const float* __restrict__ k,
                                                    const float* __restrict__ v,
                                                    float* __restrict__ ctx)
{
    extern __shared__ float sm[];
    float* Qs   = sm;
    float* Ks   = Qs + BQ * QP;
    float* Vs   = Ks + BKV * QP;
    float* Ss   = Vs + BKV * VP;
    float* mrow = Ss + BQ * SP;
    float* lrow = mrow + BQ;
    float* srow = lrow + BQ;

    const int qt  = blockIdx.x;
    const int bh  = blockIdx.y;
    const int b   = bh >> 4;
    const int h   = bh & 15;
    const int tid = threadIdx.x;
    const float scale = 0.08838834764831845f;

#pragma unroll
    for (int l = 0; l < 8; l++) {
        int idx = tid + l * 256;
        int r  = idx >> 5;
        int c4 = idx & 31;
        float4 vq = *(const float4*)(q + (size_t)(b * SEQ + qt * BQ + r) * EMB + h * HD + c4 * 4);
        float* dst = &Qs[r * QP + c4 * 4];
        dst[0] = vq.x * scale; dst[1] = vq.y * scale;
        dst[2] = vq.z * scale; dst[3] = vq.w * scale;
    }
    if (tid < BQ) { mrow[tid] = -1e30f; lrow[tid] = 0.f; }

    float acc[4][8];
#pragma unroll
    for (int i = 0; i < 4; i++)
#pragma unroll
        for (int j = 0; j < 8; j++) acc[i][j] = 0.f;

    const int ty = tid >> 4;
    const int tx = tid & 15;
    const int ro = ty * 4;
    const int co = tx * 8;

    for (int kt = 0; kt <= qt; kt++) {
        __syncthreads();
#pragma unroll
        for (int l = 0; l < 8; l++) {
            int idx = tid + l * 256;
            int r  = idx >> 5;
            int c4 = idx & 31;
            size_t goff = (size_t)(b * SEQ + kt * BKV + r) * EMB + h * HD + c4 * 4;
            float4 vk = *(const float4*)(k + goff);
            float* dk = &Ks[r * QP + c4 * 4];
            dk[0] = vk.x; dk[1] = vk.y; dk[2] = vk.z; dk[3] = vk.w;
            float4 vv = *(const float4*)(v + goff);
            *(float4*)&Vs[r * VP + c4 * 4] = vv;
        }
        __syncthreads();

        float s_[4][4];
#pragma unroll
        for (int i = 0; i < 4; i++)
#pragma unroll
            for (int j = 0; j < 4; j++) s_[i][j] = 0.f;
#pragma unroll 4
        for (int d = 0; d < HD; d++) {
            float aq[4], ak[4];
#pragma unroll
            for (int i = 0; i < 4; i++) aq[i] = Qs[(ro + i) * QP + d];
#pragma unroll
            for (int j = 0; j < 4; j++) ak[j] = Ks[(tx * 4 + j) * QP + d];
#pragma unroll
            for (int i = 0; i < 4; i++)
#pragma unroll
                for (int j = 0; j < 4; j++)
                    s_[i][j] = fmaf(aq[i], ak[j], s_[i][j]);
        }
#pragma unroll
        for (int i = 0; i < 4; i++)
#pragma unroll
            for (int j = 0; j < 4; j++) {
                int r = ro + i, c = tx * 4 + j;
                float val = s_[i][j];
                if (kt == qt && c > r) val = -1e30f;
                Ss[r * SP + c] = val;
            }
        __syncthreads();

        {
            int row = tid >> 2, seg = tid & 3;
            float pm = -1e30f;
            for (int c = seg * 16; c < seg * 16 + 16; c++)
                pm = fmaxf(pm, Ss[row * SP + c]);
            pm = fmaxf(pm, __shfl_xor_sync(0xffffffff, pm, 1));
            pm = fmaxf(pm, __shfl_xor_sync(0xffffffff, pm, 2));
            float mold = mrow[row];
            float mnew = fmaxf(mold, pm);
            float psum = 0.f;
            for (int c = seg * 16; c < seg * 16 + 16; c++) {
                float p = __expf(Ss[row * SP + c] - mnew);
                Ss[row * SP + c] = p;
                psum += p;
            }
            psum += __shfl_xor_sync(0xffffffff, psum, 1);
            psum += __shfl_xor_sync(0xffffffff, psum, 2);
            if (seg == 0) {
                float sc = __expf(mold - mnew);
                srow[row] = sc;
                lrow[row] = lrow[row] * sc + psum;
                mrow[row] = mnew;
            }
        }
        __syncthreads();

        float sc[4];
#pragma unroll
        for (int i = 0; i < 4; i++) sc[i] = srow[ro + i];
#pragma unroll
        for (int i = 0; i < 4; i++)
#pragma unroll
            for (int j = 0; j < 8; j++) acc[i][j] *= sc[i];

#pragma unroll 4
        for (int kk = 0; kk < BKV; kk++) {
            float p[4];
#pragma unroll
            for (int i = 0; i < 4; i++) p[i] = Ss[(ro + i) * SP + kk];
            float vv[8];
            *(float4*)(vv)     = *(const float4*)&Vs[kk * VP + co];
            *(float4*)(vv + 4) = *(const float4*)&Vs[kk * VP + co + 4];
#pragma unroll
            for (int i = 0; i < 4; i++)
#pragma unroll
                for (int j = 0; j < 8; j++)
                    acc[i][j] = fmaf(p[i], vv[j], acc[i][j]);
        }
    }

#pragma unroll
    for (int i = 0; i < 4; i++) {
        float inv = 1.0f / lrow[ro + i];
        size_t m = (size_t)(b * SEQ + qt * BQ + ro + i);
        float4 o0 = make_float4(acc[i][0] * inv, acc[i][1] * inv, acc[i][2] * inv, acc[i][3] * inv);
        float4 o1 = make_float4(acc[i][4] * inv, acc[i][5] * inv, acc[i][6] * inv, acc[i][7] * inv);
        *(float4*)(ctx + m * EMB + h * HD + co)     = o0;
        *(float4*)(ctx + m * EMB + h * HD + co + 4) = o1;
    }
}

// ---------------------------------------------------------------------------
// Launch
// ---------------------------------------------------------------------------
extern "C" void kernel_launch(void* const* d_in, const int* in_sizes, int n_in,
                              void* d_out, int out_size)
{
    const float* x  = (const float*)d_in[0];
    const float* Wq = (const float*)d_in[1];
    const float* Wk = (const float*)d_in[2];
    const float* Wv = (const float*)d_in[3];
    const float* Wo = (const float*)d_in[4];
    float* out = (float*)d_out;

    float *pq, *pk, *pv, *pctx;
    __half *pxh, *pxl, *pch, *pcl, *pwqh, *pwkh, *pwvh, *pwoh;
    cudaGetSymbolAddress((void**)&pq,   g_q);
    cudaGetSymbolAddress((void**)&pk,   g_k);
    cudaGetSymbolAddress((void**)&pv,   g_v);
    cudaGetSymbolAddress((void**)&pctx, g_ctx);
    cudaGetSymbolAddress((void**)&pxh,  g_xh);
    cudaGetSymbolAddress((void**)&pxl,  g_xl);
    cudaGetSymbolAddress((void**)&pch,  g_ch);
    cudaGetSymbolAddress((void**)&pcl,  g_cl);
    cudaGetSymbolAddress((void**)&pwqh, g_wqh);
    cudaGetSymbolAddress((void**)&pwkh, g_wkh);
    cudaGetSymbolAddress((void**)&pwvh, g_wvh);
    cudaGetSymbolAddress((void**)&pwoh, g_woh);

    cudaFuncSetAttribute(mma_gemm, cudaFuncAttributeMaxDynamicSharedMemorySize, SMEM_GEMM);

    // fp16 staging conversions
    int nx4 = (MTOT * EMB) / 4, nw4 = (EMB * EMB) / 4;
    cvt_hilo<<<(nx4 + 255) / 256, 256>>>(x, pxh, pxl, nx4);
    cvt_hi<<<(nw4 + 255) / 256, 256>>>(Wq, pwqh, nw4);
    cvt_hi<<<(nw4 + 255) / 256, 256>>>(Wk, pwkh, nw4);
    cvt_hi<<<(nw4 + 255) / 256, 256>>>(Wv, pwvh, nw4);
    cvt_hi<<<(nw4 + 255) / 256, 256>>>(Wo, pwoh, nw4);

    // Fused Q/K/V projections in one launch (gridDim.z = 3)
    dim3 gqkv(EMB / BN, MTOT / BM, 3);
    mma_gemm<<<gqkv, 256, SMEM_GEMM>>>(pxh, pxl, pwqh, pwkh, pwvh,
                                       pq, pk, pv, MTOT, EMB);

    int npairs = MTOT * NH * (HD / 2);
    rope_kernel<<<(npairs + 255) / 256, 256>>>(pq, pk);

    size_t smem = (size_t)(BQ * QP + BKV * QP + BKV * VP + BQ * SP + 3 * BQ) * sizeof(float);
    cudaFuncSetAttribute(flash_kernel, cudaFuncAttributeMaxDynamicSharedMemorySize, (int)smem);
    dim3 gf(SEQ / BQ, BATCH * NH);    // (32, 64)
    flash_kernel<<<gf, 256, smem>>>(pq, pk, pv, pctx);

    cvt_hilo<<<(nx4 + 255) / 256, 256>>>(pctx, pch, pcl, nx4);
    dim3 go(EMB / BN, MTOT / BM, 1);
    mma_gemm<<<go, 256, SMEM_GEMM>>>(pch, pcl, pwoh, pwoh, pwoh,
                                     out, out, out, MTOT, EMB);
}

// round 17
// speedup vs baseline: 1.6619x; 1.6619x over previous
#include <cuda_runtime.h>
#include <cuda_fp16.h>
#include <math.h>
#include <stdint.h>

#define EMB   2048
#define NH    16
#define HD    128
#define BATCH 4
#define SEQ   2048
#define MTOT  (BATCH*SEQ)   // 8192 rows
#define GK    2048          // GEMM K (fixed)

// Scratch (device globals -- allocation-free per harness rules)
__device__ float g_q[(size_t)MTOT * EMB];
__device__ float g_k[(size_t)MTOT * EMB];
__device__ float g_v[(size_t)MTOT * EMB];
__device__ float g_ctx[(size_t)MTOT * EMB];
// fp16 staging (GEMM)
__device__ __half g_xh[(size_t)MTOT * EMB];
__device__ __half g_xl[(size_t)MTOT * EMB];
__device__ __half g_ch[(size_t)MTOT * EMB];
__device__ __half g_cl[(size_t)MTOT * EMB];
__device__ __half g_wqh[(size_t)EMB * EMB];
__device__ __half g_wkh[(size_t)EMB * EMB];
__device__ __half g_wvh[(size_t)EMB * EMB];
__device__ __half g_woh[(size_t)EMB * EMB];
// fp16 staging (flash): roped+scaled q (hi/lo), roped k, v
__device__ __half g_fqh[(size_t)MTOT * EMB];
__device__ __half g_fql[(size_t)MTOT * EMB];
__device__ __half g_fkh[(size_t)MTOT * EMB];
__device__ __half g_fvh[(size_t)MTOT * EMB];

// ===========================================================================
// PTX helpers (baseline sm_80+)
// ===========================================================================
__device__ __forceinline__ uint32_t smem_u32(const void* p) {
    uint32_t a;
    asm("{ .reg .u64 t; cvta.to.shared.u64 t, %1; cvt.u32.u64 %0, t; }" : "=r"(a) : "l"(p));
    return a;
}
__device__ __forceinline__ void ldsm4(uint32_t* r, uint32_t addr) {
    asm volatile("ldmatrix.sync.aligned.m8n8.x4.shared.b16 {%0,%1,%2,%3}, [%4];"
        : "=r"(r[0]), "=r"(r[1]), "=r"(r[2]), "=r"(r[3]) : "r"(addr));
}
__device__ __forceinline__ void ldsm4t(uint32_t* r, uint32_t addr) {
    asm volatile("ldmatrix.sync.aligned.m8n8.x4.trans.shared.b16 {%0,%1,%2,%3}, [%4];"
        : "=r"(r[0]), "=r"(r[1]), "=r"(r[2]), "=r"(r[3]) : "r"(addr));
}
__device__ __forceinline__ void mma_f16(float* d, const uint32_t* a, uint32_t b0, uint32_t b1) {
    asm volatile("mma.sync.aligned.m16n8k16.row.col.f32.f16.f16.f32 "
        "{%0,%1,%2,%3}, {%4,%5,%6,%7}, {%8,%9}, {%0,%1,%2,%3};"
        : "+f"(d[0]), "+f"(d[1]), "+f"(d[2]), "+f"(d[3])
        : "r"(a[0]), "r"(a[1]), "r"(a[2]), "r"(a[3]), "r"(b0), "r"(b1));
}
__device__ __forceinline__ void cp16(uint32_t dst, const void* src) {
    asm volatile("cp.async.cg.shared.global [%0], [%1], 16;" :: "r"(dst), "l"(src));
}
#define CP_COMMIT() asm volatile("cp.async.commit_group;" ::: "memory")
#define CP_WAIT(n)  asm volatile("cp.async.wait_group %0;" :: "n"(n) : "memory")

// ===========================================================================
// Conversion kernels
// ===========================================================================
__global__ void cvt_hilo(const float* __restrict__ in, __half* __restrict__ hi,
                         __half* __restrict__ lo, int n4)
{
    int i = blockIdx.x * blockDim.x + threadIdx.x;
    if (i >= n4) return;
    float4 v = *(const float4*)(in + (size_t)i * 4);
    __half2 h0 = __floats2half2_rn(v.x, v.y);
    __half2 h1 = __floats2half2_rn(v.z, v.w);
    __half2 e0 = __floats2half2_rn(v.x - __low2float(h0), v.y - __high2float(h0));
    __half2 e1 = __floats2half2_rn(v.z - __low2float(h1), v.w - __high2float(h1));
    *(__half2*)(hi + (size_t)i * 4)     = h0;
    *(__half2*)(hi + (size_t)i * 4 + 2) = h1;
    *(__half2*)(lo + (size_t)i * 4)     = e0;
    *(__half2*)(lo + (size_t)i * 4 + 2) = e1;
}
__global__ void cvt_hi(const float* __restrict__ in, __half* __restrict__ hi, int n4)
{
    int i = blockIdx.x * blockDim.x + threadIdx.x;
    if (i >= n4) return;
    float4 v = *(const float4*)(in + (size_t)i * 4);
    *(__half2*)(hi + (size_t)i * 4)     = __floats2half2_rn(v.x, v.y);
    *(__half2*)(hi + (size_t)i * 4 + 2) = __floats2half2_rn(v.z, v.w);
}

// ===========================================================================
// fp16 2-pass HMMA GEMM (NT), 2-stage cp.async (best known config, R13).
// ===========================================================================
#define BM 128
#define BN 128
#define BKK 32
#define AST 40
#define NIT (GK / BKK)                 // 64
#define TILEB (BM * AST * 2)           // 10240
#define BUFB  (3 * TILEB)              // 30720
#define SMEM_GEMM (2 * BUFB)           // 61440

__global__ __launch_bounds__(256) void mma_gemm(const __half* __restrict__ Ah,
                                                const __half* __restrict__ Al,
                                                const __half* __restrict__ Bh,
                                                float* __restrict__ C,
                                                int M, int N)
{
    extern __shared__ char smem[];
    const uint32_t sb = smem_u32(smem);

    const int tid  = threadIdx.x;
    const int lane = tid & 31;
    const int wid  = tid >> 5;
    const int m0 = blockIdx.y * BM;
    const int n0 = blockIdx.x * BN;
    const int wm = (wid & 1) * 64;
    const int wn = (wid >> 1) * 32;

    float acc[4][4][4];
#pragma unroll
    for (int i = 0; i < 4; i++)
#pragma unroll
        for (int j = 0; j < 4; j++)
#pragma unroll
            for (int r = 0; r < 4; r++) acc[i][j][r] = 0.f;

    const int r0 = tid >> 2;
    const int c0 = tid & 3;
    const __half* Ap = Ah + (size_t)(m0 + r0) * GK + c0 * 8;
    const __half* Lp = Al + (size_t)(m0 + r0) * GK + c0 * 8;
    const __half* Bp = Bh + (size_t)(n0 + r0) * GK + c0 * 8;
    const uint32_t sA = sb + r0 * 80 + c0 * 16;

#define ISSUE(it, buf) do {                                                   \
        int kofs = (it) * BKK;                                                \
        uint32_t bb = (buf) * BUFB;                                           \
        cp16(sA + bb,                      Ap + kofs);                        \
        cp16(sA + bb + (64*80),            Ap + kofs + (size_t)64 * GK);      \
        cp16(sA + bb + TILEB,              Lp + kofs);                        \
        cp16(sA + bb + TILEB + (64*80),    Lp + kofs + (size_t)64 * GK);      \
        cp16(sA + bb + 2*TILEB,            Bp + kofs);                        \
        cp16(sA + bb + 2*TILEB + (64*80),  Bp + kofs + (size_t)64 * GK);      \
        CP_COMMIT();                                                          \
    } while (0)

    const uint32_t lrow = (lane & 15);
    const uint32_t lcol = (lane >> 4) * 8;
    const uint32_t aoff = ((wm + lrow) * AST + lcol) * 2;
    const uint32_t boff = ((wn + lrow) * AST + lcol) * 2 + 2 * TILEB;

    ISSUE(0, 0);

    for (int it = 0; it < NIT; it++) {
        const int buf = it & 1;
        if (it + 1 < NIT) {
            ISSUE(it + 1, buf ^ 1);
            CP_WAIT(1);
        } else {
            CP_WAIT(0);
        }
        __syncthreads();

        const uint32_t a_base  = sb + buf * BUFB + aoff;
        const uint32_t al_base = a_base + TILEB;
        const uint32_t b_base  = sb + buf * BUFB + boff;

#pragma unroll
        for (int ks = 0; ks < 2; ks++) {
            const uint32_t kb = ks * 32;

            uint32_t afh[4][4], bfh[2][4];
#pragma unroll
            for (int mt = 0; mt < 4; mt++)
                ldsm4(afh[mt], a_base + mt * (16 * AST * 2) + kb);
#pragma unroll
            for (int nh = 0; nh < 2; nh++)
                ldsm4(bfh[nh], b_base + nh * (16 * AST * 2) + kb);

#pragma unroll
            for (int mt = 0; mt < 4; mt++)
#pragma unroll
                for (int nt = 0; nt < 4; nt++)
                    mma_f16(acc[mt][nt], afh[mt], bfh[nt >> 1][nt & 1], bfh[nt >> 1][(nt & 1) + 2]);

            uint32_t afl[4][4];
#pragma unroll
            for (int mt = 0; mt < 4; mt++)
                ldsm4(afl[mt], al_base + mt * (16 * AST * 2) + kb);
#pragma unroll
            for (int mt = 0; mt < 4; mt++)
#pragma unroll
                for (int nt = 0; nt < 4; nt++)
                    mma_f16(acc[mt][nt], afl[mt], bfh[nt >> 1][nt & 1], bfh[nt >> 1][(nt & 1) + 2]);
        }
        __syncthreads();
    }

    const int erow = lane >> 2;
    const int ecol = (lane & 3) * 2;
#pragma unroll
    for (int mt = 0; mt < 4; mt++) {
#pragma unroll
        for (int nt = 0; nt < 4; nt++) {
            int row = m0 + wm + mt * 16 + erow;
            int col = n0 + wn + nt * 8 + ecol;
            *(float2*)(C + (size_t)row * N + col) =
                make_float2(acc[mt][nt][0], acc[mt][nt][1]);
            *(float2*)(C + (size_t)(row + 8) * N + col) =
                make_float2(acc[mt][nt][2], acc[mt][nt][3]);
        }
    }
#undef ISSUE
}

// ---------------------------------------------------------------------------
// RoPE + fp16 staging: reads fp32 q,k (projection outputs), writes
// scaled fp16 q (hi/lo split) and fp16 k. 1/sqrt(HD) folded into q here.
// ---------------------------------------------------------------------------
__global__ void rope_stage(const float* __restrict__ q, const float* __restrict__ k,
                           __half* __restrict__ qh, __half* __restrict__ ql,
                           __half* __restrict__ kh)
{
    int idx = blockIdx.x * blockDim.x + threadIdx.x;
    if (idx >= MTOT * NH * (HD / 2)) return;
    int i = idx & 63;
    int h = (idx >> 6) & 15;
    int m = idx >> 10;
    int s = m & (SEQ - 1);

    double freq = pow(10000.0, -(double)i / 64.0);
    float ang = (float)((double)s * freq);
    float sn, cs;
    sincosf(ang, &sn, &cs);
    const float scale = 0.08838834764831845f;   // 1/sqrt(128)

    size_t base = (size_t)m * EMB + h * HD + 2 * i;
    float q1 = q[base], q2 = q[base + 1];
    float qr1 = (q1 * cs - q2 * sn) * scale;
    float qr2 = (q2 * cs + q1 * sn) * scale;
    __half qh1 = __float2half_rn(qr1), qh2 = __float2half_rn(qr2);
    qh[base]     = qh1;
    qh[base + 1] = qh2;
    ql[base]     = __float2half_rn(qr1 - __half2float(qh1));
    ql[base + 1] = __float2half_rn(qr2 - __half2float(qh2));

    float k1 = k[base], k2 = k[base + 1];
    kh[base]     = __float2half_rn(k1 * cs - k2 * sn);
    kh[base + 1] = __float2half_rn(k2 * cs + k1 * sn);
}

// ===========================================================================
// Tensorized flash attention (causal). BQ=128, BKV=64, 256 thr = 8 warps,
// warp w owns rows 16w..16w+15 (full 64-col width -> warp-local softmax).
// S = (Qh+Ql)*Kh^T (2-pass HMMA), P->fp16 in-register, PV 1-pass HMMA with
// V B-fragments via ldmatrix.trans. K/V double-buffered cp.async.
// ===========================================================================
#define FBQ 128
#define FBK 64
#define QST 136    // smem row stride (halfs); 272B: 16B-aligned, conflict-free
#define KST 136
#define VST 136
#define QTILEB (FBQ * QST * 2)     // 34816
#define KTILEB (FBK * KST * 2)     // 17408
#define VTILEB (FBK * VST * 2)     // 17408
#define OFF_QH 0
#define OFF_QL QTILEB
#define OFF_K  (2 * QTILEB)
#define OFF_V  (2 * QTILEB + 2 * KTILEB)
#define SMEM_FLASH (2 * QTILEB + 2 * KTILEB + 2 * VTILEB)   // 139264

__global__ __launch_bounds__(256) void tf_flash(const __half* __restrict__ qh,
                                                const __half* __restrict__ ql,
                                                const __half* __restrict__ kh,
                                                const __half* __restrict__ vh,
                                                float* __restrict__ ctx)
{
    extern __shared__ char smem[];
    const uint32_t sb = smem_u32(smem);
    const int tid  = threadIdx.x;
    const int lane = tid & 31;
    const int wid  = tid >> 5;
    const int qt = blockIdx.x;
    const int bh = blockIdx.y;
    const int b  = bh >> 4;
    const int h  = bh & 15;
    const int q0 = qt * FBQ;
    const int ntiles = 2 * qt + 2;

    // ---- Q load (both arrays), part of cp.async group 0 ----
#pragma unroll
    for (int t = 0; t < 8; t++) {
        int idx = tid + t * 256;          // 0..2047
        int r = idx >> 4, c = idx & 15;
        size_t g = (size_t)(b * SEQ + q0 + r) * EMB + h * HD + c * 8;
        uint32_t s = r * (QST * 2) + c * 16;
        cp16(sb + OFF_QH + s, qh + g);
        cp16(sb + OFF_QL + s, ql + g);
    }

    // KV tile issue (64 rows x 16 chunks per array)
#define KV_ISSUE(kt, buf) do {                                                \
        for (int t = 0; t < 4; t++) {                                         \
            int idx = tid + t * 256;                                          \
            int r = idx >> 4, c = idx & 15;                                   \
            size_t g = (size_t)(b * SEQ + (kt) * FBK + r) * EMB + h * HD + c * 8; \
            cp16(sb + OFF_K + (buf) * KTILEB + r * (KST * 2) + c * 16, kh + g);   \
            cp16(sb + OFF_V + (buf) * VTILEB + r * (VST * 2) + c * 16, vh + g);   \
        }                                                                     \
        CP_COMMIT();                                                          \
    } while (0)

    KV_ISSUE(0, 0);
    if (ntiles > 1) KV_ISSUE(1, 1);

    // fragment base addresses
    const uint32_t qrow = 16 * wid + (lane & 15);
    const uint32_t c8   = (lane >> 4) * 8;
    const uint32_t qh_base = sb + OFF_QH + (qrow * QST + c8) * 2;
    const uint32_t ql_base = sb + OFF_QL + (qrow * QST + c8) * 2;
    const uint32_t koff = ((lane & 15) * KST + c8) * 2;
    const uint32_t voff = (((lane & 7) + 8 * ((lane >> 3) & 1)) * VST + 8 * (lane >> 4)) * 2;

    // softmax state + O accumulators
    float m1 = -1e30f, m2 = -1e30f, l1 = 0.f, l2 = 0.f;
    float oacc[16][4];
#pragma unroll
    for (int i = 0; i < 16; i++)
#pragma unroll
        for (int r = 0; r < 4; r++) oacc[i][r] = 0.f;

    const int r1g = q0 + 16 * wid + (lane >> 2);   // global row (low)

    for (int kt = 0; kt < ntiles; kt++) {
        const int buf = kt & 1;
        if (kt + 1 < ntiles) { CP_WAIT(1); } else { CP_WAIT(0); }
        __syncthreads();

        const uint32_t kbase = sb + OFF_K + buf * KTILEB + koff;
        const uint32_t vbase = sb + OFF_V + buf * VTILEB + voff;

        // ---- S = Q K^T (2-pass) ----
        float sacc[8][4];
#pragma unroll
        for (int i = 0; i < 8; i++)
#pragma unroll
            for (int r = 0; r < 4; r++) sacc[i][r] = 0.f;

#pragma unroll
        for (int ks = 0; ks < 8; ks++) {
            uint32_t aqh[4], aql[4];
            ldsm4(aqh, qh_base + ks * 32);
            ldsm4(aql, ql_base + ks * 32);
#pragma unroll
            for (int ng = 0; ng < 4; ng++) {
                uint32_t bk[4];
                ldsm4(bk, kbase + ng * (16 * KST * 2) + ks * 32);
                mma_f16(sacc[2 * ng],     aqh, bk[0], bk[2]);
                mma_f16(sacc[2 * ng + 1], aqh, bk[1], bk[3]);
                mma_f16(sacc[2 * ng],     aql, bk[0], bk[2]);
                mma_f16(sacc[2 * ng + 1], aql, bk[1], bk[3]);
            }
        }

        // ---- causal mask (diagonal-crossing tiles only) ----
        if (kt >= 2 * qt) {
            int cb = kt * FBK + 2 * (lane & 3);
#pragma unroll
            for (int nt = 0; nt < 8; nt++) {
                int c0 = cb + 8 * nt, c1 = c0 + 1;
                if (c0 > r1g)     sacc[nt][0] = -1e30f;
                if (c1 > r1g)     sacc[nt][1] = -1e30f;
                if (c0 > r1g + 8) sacc[nt][2] = -1e30f;
                if (c1 > r1g + 8) sacc[nt][3] = -1e30f;
            }
        }

        // ---- online softmax (warp-local; quad shuffles) ----
        float mx1 = -1e30f, mx2 = -1e30f;
#pragma unroll
        for (int nt = 0; nt < 8; nt++) {
            mx1 = fmaxf(mx1, fmaxf(sacc[nt][0], sacc[nt][1]));
            mx2 = fmaxf(mx2, fmaxf(sacc[nt][2], sacc[nt][3]));
        }
        mx1 = fmaxf(mx1, __shfl_xor_sync(0xffffffff, mx1, 1));
        mx1 = fmaxf(mx1, __shfl_xor_sync(0xffffffff, mx1, 2));
        mx2 = fmaxf(mx2, __shfl_xor_sync(0xffffffff, mx2, 1));
        mx2 = fmaxf(mx2, __shfl_xor_sync(0xffffffff, mx2, 2));

        float mn1 = fmaxf(m1, mx1), a1 = __expf(m1 - mn1); m1 = mn1;
        float mn2 = fmaxf(m2, mx2), a2 = __expf(m2 - mn2); m2 = mn2;

        float sum1 = 0.f, sum2 = 0.f;
        uint32_t pfrag[8][2];
#pragma unroll
        for (int nt = 0; nt < 8; nt++) {
            float p0 = __expf(sacc[nt][0] - m1);
            float p1 = __expf(sacc[nt][1] - m1);
            float p2 = __expf(sacc[nt][2] - m2);
            float p3 = __expf(sacc[nt][3] - m2);
            sum1 += p0 + p1; sum2 += p2 + p3;
            __half2 hp0 = __floats2half2_rn(p0, p1);
            __half2 hp1 = __floats2half2_rn(p2, p3);
            pfrag[nt][0] = *(uint32_t*)&hp0;
            pfrag[nt][1] = *(uint32_t*)&hp1;
        }
        sum1 += __shfl_xor_sync(0xffffffff, sum1, 1);
        sum1 += __shfl_xor_sync(0xffffffff, sum1, 2);
        sum2 += __shfl_xor_sync(0xffffffff, sum2, 1);
        sum2 += __shfl_xor_sync(0xffffffff, sum2, 2);
        l1 = l1 * a1 + sum1;
        l2 = l2 * a2 + sum2;

#pragma unroll
        for (int i = 0; i < 16; i++) {
            oacc[i][0] *= a1; oacc[i][1] *= a1;
            oacc[i][2] *= a2; oacc[i][3] *= a2;
        }

        // ---- O += P V (1-pass) ----
#pragma unroll
        for (int kk = 0; kk < 4; kk++) {
            uint32_t pa[4] = { pfrag[2 * kk][0], pfrag[2 * kk][1],
                               pfrag[2 * kk + 1][0], pfrag[2 * kk + 1][1] };
#pragma unroll
            for (int dg = 0; dg < 8; dg++) {
                uint32_t bv[4];
                ldsm4t(bv, vbase + kk * (16 * VST * 2) + dg * 32);
                mma_f16(oacc[2 * dg],     pa, bv[0], bv[1]);
                mma_f16(oacc[2 * dg + 1], pa, bv[2], bv[3]);
            }
        }

        __syncthreads();
        if (kt + 2 < ntiles) KV_ISSUE(kt + 2, buf);
    }

    // ---- epilogue ----
    float il1 = 1.0f / l1, il2 = 1.0f / l2;
    size_t row1 = (size_t)(b * SEQ) + r1g;
#pragma unroll
    for (int nt2 = 0; nt2 < 16; nt2++) {
        size_t d = h * HD + 8 * nt2 + 2 * (lane & 3);
        *(float2*)(ctx + row1 * EMB + d) =
            make_float2(oacc[nt2][0] * il1, oacc[nt2][1] * il1);
        *(float2*)(ctx + (row1 + 8) * EMB + d) =
            make_float2(oacc[nt2][2] * il2, oacc[nt2][3] * il2);
    }
#undef KV_ISSUE
}

// ---------------------------------------------------------------------------
// Launch
// ---------------------------------------------------------------------------
extern "C" void kernel_launch(void* const* d_in, const int* in_sizes, int n_in,
                              void* d_out, int out_size)
{
    const float* x  = (const float*)d_in[0];
    const float* Wq = (const float*)d_in[1];
    const float* Wk = (const float*)d_in[2];
    const float* Wv = (const float*)d_in[3];
    const float* Wo = (const float*)d_in[4];
    float* out = (float*)d_out;

    float *pq, *pk, *pv, *pctx;
    __half *pxh, *pxl, *pch, *pcl, *pwqh, *pwkh, *pwvh, *pwoh;
    __half *pfqh, *pfql, *pfkh, *pfvh;
    cudaGetSymbolAddress((void**)&pq,   g_q);
    cudaGetSymbolAddress((void**)&pk,   g_k);
    cudaGetSymbolAddress((void**)&pv,   g_v);
    cudaGetSymbolAddress((void**)&pctx, g_ctx);
    cudaGetSymbolAddress((void**)&pxh,  g_xh);
    cudaGetSymbolAddress((void**)&pxl,  g_xl);
    cudaGetSymbolAddress((void**)&pch,  g_ch);
    cudaGetSymbolAddress((void**)&pcl,  g_cl);
    cudaGetSymbolAddress((void**)&pwqh, g_wqh);
    cudaGetSymbolAddress((void**)&pwkh, g_wkh);
    cudaGetSymbolAddress((void**)&pwvh, g_wvh);
    cudaGetSymbolAddress((void**)&pwoh, g_woh);
    cudaGetSymbolAddress((void**)&pfqh, g_fqh);
    cudaGetSymbolAddress((void**)&pfql, g_fql);
    cudaGetSymbolAddress((void**)&pfkh, g_fkh);
    cudaGetSymbolAddress((void**)&pfvh, g_fvh);

    cudaFuncSetAttribute(mma_gemm, cudaFuncAttributeMaxDynamicSharedMemorySize, SMEM_GEMM);
    cudaFuncSetAttribute(tf_flash, cudaFuncAttributeMaxDynamicSharedMemorySize, SMEM_FLASH);

    // fp16 staging conversions
    int nx4 = (MTOT * EMB) / 4, nw4 = (EMB * EMB) / 4;
    cvt_hilo<<<(nx4 + 255) / 256, 256>>>(x, pxh, pxl, nx4);
    cvt_hi<<<(nw4 + 255) / 256, 256>>>(Wq, pwqh, nw4);
    cvt_hi<<<(nw4 + 255) / 256, 256>>>(Wk, pwkh, nw4);
    cvt_hi<<<(nw4 + 255) / 256, 256>>>(Wv, pwvh, nw4);
    cvt_hi<<<(nw4 + 255) / 256, 256>>>(Wo, pwoh, nw4);

    dim3 gg(EMB / BN, MTOT / BM);     // (16, 64)
    mma_gemm<<<gg, 256, SMEM_GEMM>>>(pxh, pxl, pwqh, pq, MTOT, EMB);
    mma_gemm<<<gg, 256, SMEM_GEMM>>>(pxh, pxl, pwkh, pk, MTOT, EMB);
    mma_gemm<<<gg, 256, SMEM_GEMM>>>(pxh, pxl, pwvh, pv, MTOT, EMB);

    int npairs = MTOT * NH * (HD / 2);
    rope_stage<<<(npairs + 255) / 256, 256>>>(pq, pk, pfqh, pfql, pfkh);
    cvt_hi<<<(nx4 + 255) / 256, 256>>>(pv, pfvh, nx4);

    dim3 gf(SEQ / FBQ, BATCH * NH);   // (16, 64)
    tf_flash<<<gf, 256, SMEM_FLASH>>>(pfqh, pfql, pfkh, pfvh, pctx);

    cvt_hilo<<<(nx4 + 255) / 256, 256>>>(pctx, pch, pcl, nx4);
    mma_gemm<<<gg, 256, SMEM_GEMM>>>(pch, pcl, pwoh, out, MTOT, EMB);
}